// round 12
// baseline (speedup 1.0000x reference)
#include <cuda_runtime.h>
#include <math.h>

// ---------------- constants ----------------
#define B_      2
#define N_      4096
#define C_      256
#define NC_     150
#define T_      4
#define TN_     16384          // T_*N_
#define ROWS_   32768          // B_*TN_
#define HID_    1024
#define NH_     8
#define HD_     32
#define IMG_    64
#define SPLITK_ 8

// ---------------- scratch (device globals; no allocation) ----------------
__device__ float g_xf  [8u*4096u*256u];       // (B*T, N, C)
__device__ float g_clc [2u*16384u*150u];      // (B, TN, nc) rows (ungated)
__device__ float g_g1  [2u*16384u];           // per-row gate for z columns
__device__ float g_g2  [2u*16384u];           // per-row gate for clc
__device__ float g_soft[8u*150u*4096u];       // softmax(center)
__device__ float g_cenp[8u*8u*150u*256u];     // splitK partials: (split,B*T,nc,C)
__device__ float g_cin [2u*150u*256u];        // LN(C_in)
__device__ float g_kb  [2u*150u*256u];
__device__ float g_vb  [2u*150u*256u];
__device__ float g_q   [2u*4096u*256u];
__device__ float g_ao  [2u*4096u*256u];       // attention out, reused for fc2 out
__device__ float g_pj  [2u*4096u*256u];       // proj out
__device__ float g_h   [2u*4096u*1024u];      // fc1 out
__device__ float g_h2  [2u*4096u*1024u];      // conv out
__device__ float g_p1h [256];
__device__ float g_p2h [256];

// ---------------- reduction helpers (blockDim.x == 256) ----------------
__device__ __forceinline__ float bsum(float v) {
    __shared__ float sh[32];
    #pragma unroll
    for (int o = 16; o > 0; o >>= 1) v += __shfl_xor_sync(0xffffffffu, v, o);
    int lane = threadIdx.x & 31, w = threadIdx.x >> 5;
    if (lane == 0) sh[w] = v;
    __syncthreads();
    float r = (threadIdx.x < (blockDim.x >> 5)) ? sh[threadIdx.x] : 0.f;
    if (threadIdx.x < 32) {
        #pragma unroll
        for (int o = 16; o > 0; o >>= 1) r += __shfl_xor_sync(0xffffffffu, r, o);
    }
    if (threadIdx.x == 0) sh[0] = r;
    __syncthreads();
    r = sh[0];
    __syncthreads();
    return r;
}

__device__ __forceinline__ float bmax(float v) {
    __shared__ float sh[32];
    #pragma unroll
    for (int o = 16; o > 0; o >>= 1) v = fmaxf(v, __shfl_xor_sync(0xffffffffu, v, o));
    int lane = threadIdx.x & 31, w = threadIdx.x >> 5;
    if (lane == 0) sh[w] = v;
    __syncthreads();
    float r = (threadIdx.x < (blockDim.x >> 5)) ? sh[threadIdx.x] : -1e30f;
    if (threadIdx.x < 32) {
        #pragma unroll
        for (int o = 16; o > 0; o >>= 1) r = fmaxf(r, __shfl_xor_sync(0xffffffffu, r, o));
    }
    if (threadIdx.x == 0) sh[0] = r;
    __syncthreads();
    r = sh[0];
    __syncthreads();
    return r;
}

// ---------------- generic tiled GEMM (64x64x16, 256 thr, 4x4 microtile) ----
// TRB: B is (N,K) row-major (PyTorch Linear, contract last dims). else (K,N).
// GELUA: exact GELU applied to A elements on load.
template<bool TRB, bool GELUA>
__global__ void __launch_bounds__(256) gemm_k(
    const float* __restrict__ A, const float* __restrict__ Bp,
    const float* __restrict__ bias, float* __restrict__ Cp,
    int M, int Nn, int K, long sA, long sB, long sC,
    float postscale)
{
    int batch = blockIdx.z;
    const float* Ab = A + (long)batch * sA;
    const float* Bb = Bp + (long)batch * sB;
    float* Cb = Cp + (long)batch * sC;
    int m0 = blockIdx.y * 64, n0 = blockIdx.x * 64;
    __shared__ float As[16][64];
    __shared__ float Bs[16][64];
    int tid = threadIdx.x;
    int tx = tid & 15, ty = tid >> 4;
    float acc[4][4] = {};
    for (int kb = 0; kb < K; kb += 16) {
        #pragma unroll
        for (int i = 0; i < 4; i++) {
            int e = tid + i * 256;
            int mm = e >> 4, kk = e & 15;
            int gm = m0 + mm;
            float v = 0.f;
            if (gm < M) v = Ab[(long)gm * K + kb + kk];
            if (GELUA) v = 0.5f * v * (1.f + erff(v * 0.70710678118654752f));
            As[kk][mm] = v;
        }
        #pragma unroll
        for (int i = 0; i < 4; i++) {
            int e = tid + i * 256;
            if (TRB) {
                int nn = e >> 4, kk = e & 15;
                int gn = n0 + nn;
                Bs[kk][nn] = (gn < Nn) ? Bb[(long)gn * K + kb + kk] : 0.f;
            } else {
                int kk = e >> 6, nn = e & 63;
                int gn = n0 + nn;
                Bs[kk][nn] = (gn < Nn) ? Bb[(long)(kb + kk) * Nn + gn] : 0.f;
            }
        }
        __syncthreads();
        #pragma unroll
        for (int kk = 0; kk < 16; kk++) {
            float4 av = *(const float4*)&As[kk][ty * 4];
            float4 bv = *(const float4*)&Bs[kk][tx * 4];
            float a[4] = {av.x, av.y, av.z, av.w};
            float b[4] = {bv.x, bv.y, bv.z, bv.w};
            #pragma unroll
            for (int i = 0; i < 4; i++)
                #pragma unroll
                for (int j = 0; j < 4; j++)
                    acc[i][j] += a[i] * b[j];
        }
        __syncthreads();
    }
    #pragma unroll
    for (int i = 0; i < 4; i++) {
        int gm = m0 + ty * 4 + i;
        if (gm >= M) continue;
        #pragma unroll
        for (int j = 0; j < 4; j++) {
            int gn = n0 + tx * 4 + j;
            if (gn >= Nn) continue;
            float v = acc[i][j];
            if (bias) v += bias[gn];
            Cb[(long)gm * Nn + gn] = v * postscale;
        }
    }
}

// ---------------- cen GEMM (64m x 128n x 16k, 256 thr, 4x8 split microtile) --
// Register-prefetch pipelined. Plain-store splitK partials (no atomics):
// Cp layout (split, B*T, nc, C). Consumer (cin_k) sums the partials.
__global__ void __launch_bounds__(256) gemm_cen_k(
    const float* __restrict__ A, const float* __restrict__ Bx,
    float* __restrict__ Cp)
{
    int zb = blockIdx.z;
    int batch = zb / SPLITK_;
    int ks = zb - batch * SPLITK_;
    const int kLen = N_ / SPLITK_;           // 512
    const float* Ab = A + (long)batch * NC_ * N_;
    const float* Bb = Bx + (long)batch * N_ * C_;
    float* Cb = Cp + ((long)ks * (B_ * T_) + batch) * NC_ * C_;
    int m0 = blockIdx.y * 64, n0 = blockIdx.x * 128;
    __shared__ float As[16][68];
    __shared__ float Bs[16][132];
    const int tid = threadIdx.x;
    const int tx = tid & 15, ty = tid >> 4;
    const int amm = tid >> 2, ak4 = (tid & 3) * 4;
    const bool aok = (m0 + amm) < NC_;
    const int bk0 = tid >> 5,        bn0 = (tid & 31) * 4;          // B slot i=0
    const int bk1 = (tid + 256) >> 5, bn1 = ((tid + 256) & 31) * 4; // B slot i=1
    float acc[4][8] = {};
    int kbeg = ks * kLen;
    const float4 z4 = {0.f, 0.f, 0.f, 0.f};
    float4 pa = aok ? *(const float4*)&Ab[(long)(m0 + amm) * N_ + kbeg + ak4] : z4;
    float4 pb0 = *(const float4*)&Bb[(long)(kbeg + bk0) * C_ + n0 + bn0];
    float4 pb1 = *(const float4*)&Bb[(long)(kbeg + bk1) * C_ + n0 + bn1];
    for (int kt = 0; kt < kLen; kt += 16) {
        As[ak4 + 0][amm] = pa.x;
        As[ak4 + 1][amm] = pa.y;
        As[ak4 + 2][amm] = pa.z;
        As[ak4 + 3][amm] = pa.w;
        *(float4*)&Bs[bk0][bn0] = pb0;
        *(float4*)&Bs[bk1][bn1] = pb1;
        __syncthreads();
        if (kt + 16 < kLen) {
            int kb = kbeg + kt + 16;
            pa = aok ? *(const float4*)&Ab[(long)(m0 + amm) * N_ + kb + ak4] : z4;
            pb0 = *(const float4*)&Bb[(long)(kb + bk0) * C_ + n0 + bn0];
            pb1 = *(const float4*)&Bb[(long)(kb + bk1) * C_ + n0 + bn1];
        }
        #pragma unroll
        for (int kk = 0; kk < 16; kk++) {
            float4 a0 = *(const float4*)&As[kk][ty * 4];
            float4 b0 = *(const float4*)&Bs[kk][tx * 4];
            float4 b1 = *(const float4*)&Bs[kk][tx * 4 + 64];
            float a[4] = {a0.x, a0.y, a0.z, a0.w};
            float b[8] = {b0.x, b0.y, b0.z, b0.w, b1.x, b1.y, b1.z, b1.w};
            #pragma unroll
            for (int i = 0; i < 4; i++)
                #pragma unroll
                for (int j = 0; j < 8; j++)
                    acc[i][j] += a[i] * b[j];
        }
        __syncthreads();
    }
    #pragma unroll
    for (int i = 0; i < 4; i++) {
        int gm = m0 + ty * 4 + i;
        if (gm >= NC_) continue;
        float* crow = Cb + (long)gm * C_ + n0;
        #pragma unroll
        for (int jh = 0; jh < 2; jh++) {
            int cb = tx * 4 + jh * 64;
            float4 v;
            v.x = acc[i][jh * 4 + 0];
            v.y = acc[i][jh * 4 + 1];
            v.z = acc[i][jh * 4 + 2];
            v.w = acc[i][jh * 4 + 3];
            *(float4*)&crow[cb] = v;
        }
    }
}

// ---------------- big tiled GEMM (128x128x16, 256 thr, 8x8 split microtile) --
// Register-prefetch pipelined. M % 128 == 0, Nn % 128 == 0, K % 16 == 0.
// B is (N,K) row-major (Linear weight). GELUA: exact GELU on A at smem store.
template<bool GELUA>
__global__ void __launch_bounds__(256, 2) gemm128_k(
    const float* __restrict__ A, const float* __restrict__ Bp,
    const float* __restrict__ bias, float* __restrict__ Cp,
    int Nn, int K, float postscale)
{
    const int m0 = blockIdx.y * 128, n0 = blockIdx.x * 128;
    __shared__ float As[16][132];
    __shared__ float Bs[16][132];
    const int tid = threadIdx.x;
    const int tx = tid & 15, ty = tid >> 4;
    const int mm0 = tid >> 2, k40 = (tid & 3) * 4;
    const int mm1 = (tid + 256) >> 2, k41 = ((tid + 256) & 3) * 4;
    float acc[8][8] = {};
    float4 pa0, pa1, pb0, pb1;
    pa0 = *(const float4*)&A [(long)(m0 + mm0) * K + k40];
    pa1 = *(const float4*)&A [(long)(m0 + mm1) * K + k41];
    pb0 = *(const float4*)&Bp[(long)(n0 + mm0) * K + k40];
    pb1 = *(const float4*)&Bp[(long)(n0 + mm1) * K + k41];
    for (int kb = 0; kb < K; kb += 16) {
        float4 va0 = pa0, va1 = pa1;
        if (GELUA) {
            va0.x = 0.5f * va0.x * (1.f + erff(va0.x * 0.70710678118654752f));
            va0.y = 0.5f * va0.y * (1.f + erff(va0.y * 0.70710678118654752f));
            va0.z = 0.5f * va0.z * (1.f + erff(va0.z * 0.70710678118654752f));
            va0.w = 0.5f * va0.w * (1.f + erff(va0.w * 0.70710678118654752f));
            va1.x = 0.5f * va1.x * (1.f + erff(va1.x * 0.70710678118654752f));
            va1.y = 0.5f * va1.y * (1.f + erff(va1.y * 0.70710678118654752f));
            va1.z = 0.5f * va1.z * (1.f + erff(va1.z * 0.70710678118654752f));
            va1.w = 0.5f * va1.w * (1.f + erff(va1.w * 0.70710678118654752f));
        }
        As[k40 + 0][mm0] = va0.x; As[k40 + 1][mm0] = va0.y;
        As[k40 + 2][mm0] = va0.z; As[k40 + 3][mm0] = va0.w;
        As[k41 + 0][mm1] = va1.x; As[k41 + 1][mm1] = va1.y;
        As[k41 + 2][mm1] = va1.z; As[k41 + 3][mm1] = va1.w;
        Bs[k40 + 0][mm0] = pb0.x; Bs[k40 + 1][mm0] = pb0.y;
        Bs[k40 + 2][mm0] = pb0.z; Bs[k40 + 3][mm0] = pb0.w;
        Bs[k41 + 0][mm1] = pb1.x; Bs[k41 + 1][mm1] = pb1.y;
        Bs[k41 + 2][mm1] = pb1.z; Bs[k41 + 3][mm1] = pb1.w;
        __syncthreads();
        if (kb + 16 < K) {
            int kn = kb + 16;
            pa0 = *(const float4*)&A [(long)(m0 + mm0) * K + kn + k40];
            pa1 = *(const float4*)&A [(long)(m0 + mm1) * K + kn + k41];
            pb0 = *(const float4*)&Bp[(long)(n0 + mm0) * K + kn + k40];
            pb1 = *(const float4*)&Bp[(long)(n0 + mm1) * K + kn + k41];
        }
        #pragma unroll
        for (int kk = 0; kk < 16; kk++) {
            float4 a0 = *(const float4*)&As[kk][ty * 4];
            float4 a1 = *(const float4*)&As[kk][ty * 4 + 64];
            float4 b0 = *(const float4*)&Bs[kk][tx * 4];
            float4 b1 = *(const float4*)&Bs[kk][tx * 4 + 64];
            float a[8] = {a0.x, a0.y, a0.z, a0.w, a1.x, a1.y, a1.z, a1.w};
            float b[8] = {b0.x, b0.y, b0.z, b0.w, b1.x, b1.y, b1.z, b1.w};
            #pragma unroll
            for (int i = 0; i < 8; i++)
                #pragma unroll
                for (int j = 0; j < 8; j++)
                    acc[i][j] += a[i] * b[j];
        }
        __syncthreads();
    }
    #pragma unroll
    for (int ih = 0; ih < 2; ih++) {
        #pragma unroll
        for (int ii = 0; ii < 4; ii++) {
            int gm = m0 + ty * 4 + ih * 64 + ii;
            float* crow = Cp + (long)gm * Nn + n0;
            #pragma unroll
            for (int jh = 0; jh < 2; jh++) {
                int cb = tx * 4 + jh * 64;
                float4 v;
                v.x = acc[ih * 4 + ii][jh * 4 + 0];
                v.y = acc[ih * 4 + ii][jh * 4 + 1];
                v.z = acc[ih * 4 + ii][jh * 4 + 2];
                v.w = acc[ih * 4 + ii][jh * 4 + 3];
                if (bias) {
                    v.x += bias[n0 + cb + 0];
                    v.y += bias[n0 + cb + 1];
                    v.z += bias[n0 + cb + 2];
                    v.w += bias[n0 + cb + 3];
                }
                v.x *= postscale; v.y *= postscale;
                v.z *= postscale; v.w *= postscale;
                *(float4*)&crow[cb] = v;
            }
        }
    }
}

// ---------------- N-guarded 128x128 GEMM (for N not multiple of 128) --------
__global__ void __launch_bounds__(256, 2) gemm128n_k(
    const float* __restrict__ A, const float* __restrict__ Bp,
    float* __restrict__ Cp, int Nn, int K)
{
    const int m0 = blockIdx.y * 128, n0 = blockIdx.x * 128;
    __shared__ float As[16][132];
    __shared__ float Bs[16][132];
    const int tid = threadIdx.x;
    const int tx = tid & 15, ty = tid >> 4;
    const int mm0 = tid >> 2, k40 = (tid & 3) * 4;
    const int mm1 = (tid + 256) >> 2, k41 = ((tid + 256) & 3) * 4;
    const bool b0ok = (n0 + mm0 < Nn);
    const bool b1ok = (n0 + mm1 < Nn);
    float acc[8][8] = {};
    float4 pa0, pa1, pb0, pb1;
    const float4 z4 = {0.f, 0.f, 0.f, 0.f};
    pa0 = *(const float4*)&A[(long)(m0 + mm0) * K + k40];
    pa1 = *(const float4*)&A[(long)(m0 + mm1) * K + k41];
    pb0 = b0ok ? *(const float4*)&Bp[(long)(n0 + mm0) * K + k40] : z4;
    pb1 = b1ok ? *(const float4*)&Bp[(long)(n0 + mm1) * K + k41] : z4;
    for (int kb = 0; kb < K; kb += 16) {
        As[k40 + 0][mm0] = pa0.x; As[k40 + 1][mm0] = pa0.y;
        As[k40 + 2][mm0] = pa0.z; As[k40 + 3][mm0] = pa0.w;
        As[k41 + 0][mm1] = pa1.x; As[k41 + 1][mm1] = pa1.y;
        As[k41 + 2][mm1] = pa1.z; As[k41 + 3][mm1] = pa1.w;
        Bs[k40 + 0][mm0] = pb0.x; Bs[k40 + 1][mm0] = pb0.y;
        Bs[k40 + 2][mm0] = pb0.z; Bs[k40 + 3][mm0] = pb0.w;
        Bs[k41 + 0][mm1] = pb1.x; Bs[k41 + 1][mm1] = pb1.y;
        Bs[k41 + 2][mm1] = pb1.z; Bs[k41 + 3][mm1] = pb1.w;
        __syncthreads();
        if (kb + 16 < K) {
            int kn = kb + 16;
            pa0 = *(const float4*)&A[(long)(m0 + mm0) * K + kn + k40];
            pa1 = *(const float4*)&A[(long)(m0 + mm1) * K + kn + k41];
            pb0 = b0ok ? *(const float4*)&Bp[(long)(n0 + mm0) * K + kn + k40] : z4;
            pb1 = b1ok ? *(const float4*)&Bp[(long)(n0 + mm1) * K + kn + k41] : z4;
        }
        #pragma unroll
        for (int kk = 0; kk < 16; kk++) {
            float4 a0 = *(const float4*)&As[kk][ty * 4];
            float4 a1 = *(const float4*)&As[kk][ty * 4 + 64];
            float4 b0 = *(const float4*)&Bs[kk][tx * 4];
            float4 b1 = *(const float4*)&Bs[kk][tx * 4 + 64];
            float a[8] = {a0.x, a0.y, a0.z, a0.w, a1.x, a1.y, a1.z, a1.w};
            float b[8] = {b0.x, b0.y, b0.z, b0.w, b1.x, b1.y, b1.z, b1.w};
            #pragma unroll
            for (int i = 0; i < 8; i++)
                #pragma unroll
                for (int j = 0; j < 8; j++)
                    acc[i][j] += a[i] * b[j];
        }
        __syncthreads();
    }
    #pragma unroll
    for (int ih = 0; ih < 2; ih++) {
        #pragma unroll
        for (int ii = 0; ii < 4; ii++) {
            int gm = m0 + ty * 4 + ih * 64 + ii;
            float* crow = Cp + (long)gm * Nn;
            #pragma unroll
            for (int jh = 0; jh < 2; jh++) {
                #pragma unroll
                for (int jj = 0; jj < 4; jj++) {
                    int gn = n0 + tx * 4 + jh * 64 + jj;
                    if (gn < Nn) crow[gn] = acc[ih * 4 + ii][jh * 4 + jj];
                }
            }
        }
    }
}

// ---------------- misc kernels ----------------
__global__ void prompt_k(const float* __restrict__ p1, const float* __restrict__ p2,
                         float* p1h, float* p2h) {
    int c = threadIdx.x;
    float v1 = (c < NC_) ? p1[c] : 0.f;
    float v2 = (c < NC_) ? p2[c] : 0.f;
    float s1 = bsum(v1 * v1);
    float s2 = bsum(v2 * v2);
    if (c < NC_) {
        p1h[c] = v1 / fmaxf(sqrtf(s1), 1e-12f);
        p2h[c] = v2 / fmaxf(sqrtf(s2), 1e-12f);
    }
}

__global__ void build_xf_k(const float* __restrict__ x, const float* __restrict__ mem,
                           float* __restrict__ xf) {
    long idx = (long)blockIdx.x * 256 + threadIdx.x;
    long e = idx * 4;
    long r = e >> 8;
    int c = (int)(e & 255);
    int b = (int)(r >> 14);
    int rem = (int)(r & 16383);
    int tau = rem >> 12;
    int n = rem & 4095;
    const float* src = (tau < 3)
        ? mem + ((((long)(b * 3 + tau)) * N_ + n) << 8) + c
        : x + ((((long)b) * N_ + n) << 8) + c;
    *(float4*)(xf + e) = *(const float4*)src;
}

// gate over z columns, direct from (B, nc, TN) layout. thread-per-row m.
__global__ void gate_z_k(const float* __restrict__ z,
                         const float* __restrict__ p1h, float* __restrict__ gg1) {
    __shared__ float ph[NC_];
    int tid = threadIdx.x;
    if (tid < NC_) ph[tid] = p1h[tid];
    __syncthreads();
    long r = (long)blockIdx.x * 256 + tid;
    int b = (int)(r >> 14);
    int m = (int)(r & 16383);
    const float* zp = z + (long)b * NC_ * TN_ + m;
    float ss = 0.f, dp = 0.f;
    #pragma unroll 5
    for (int k = 0; k < NC_; k++) {
        float v = zp[(long)k * TN_];
        ss += v * v; dp += v * ph[k];
    }
    float g = dp / fmaxf(sqrtf(ss), 1e-12f);
    gg1[r] = fminf(fmaxf(g, 0.f), 1.f);
}

// gate over clc rows (row-major). 8 warps/block, 1 row/warp.
__global__ void gate_c_k(const float* __restrict__ clc,
                         const float* __restrict__ p2h, float* __restrict__ gg2) {
    int w = threadIdx.x >> 5, lane = threadIdx.x & 31;
    long r = (long)blockIdx.x * 8 + w;
    const float* row = clc + r * NC_;
    float ss = 0.f, dp = 0.f;
    #pragma unroll
    for (int i = 0; i < 5; i++) {
        int k = lane + i * 32;
        float v = (k < NC_) ? row[k] : 0.f;
        float pk = (k < NC_) ? p2h[k] : 0.f;
        ss += v * v; dp += v * pk;
    }
    #pragma unroll
    for (int o = 16; o > 0; o >>= 1) {
        ss += __shfl_xor_sync(0xffffffffu, ss, o);
        dp += __shfl_xor_sync(0xffffffffu, dp, o);
    }
    float g = dp / fmaxf(sqrtf(ss), 1e-12f);
    g = fminf(fmaxf(g, 0.f), 1.f);
    if (lane == 0) gg2[r] = g;
}

// dual GEMM: 0.5*((g1.zT)@tdt1 + (g2.clc)@tdt2).
// 128m x 64n tile, 8x4 dual microtile (1.5 B-LDS/FMA). Load tiles and the
// scatter-staging buffer share a smem union (phases separated by barriers).
__global__ void __launch_bounds__(256) tdt_k(
    const float* __restrict__ z, const float* __restrict__ gcl,
    const float* __restrict__ gg1, const float* __restrict__ gg2,
    const float* __restrict__ t1, const float* __restrict__ t2,
    float* __restrict__ ocxz, float* __restrict__ oasg)
{
    __shared__ union {
        struct {
            float A1[16][132];
            float A2[16][132];
            float B1[16][64];
            float B2[16][64];
        } p;
        float Cs[128][65];
    } u;
    __shared__ float G1[128], G2[128];
    int m0 = blockIdx.y * 128, n0 = blockIdx.x * 64;
    int tid = threadIdx.x, tx = tid & 15, ty = tid >> 4;
    if (tid < 128) {
        G1[tid] = gg1[m0 + tid];
        G2[tid] = gg2[m0 + tid];
    }
    // batch/base for the z-sourced A1 tile (m-tile never crosses batch: 128|16384)
    const int bz = m0 >> 14;
    const int mz = m0 & 16383;
    const float* zb = z + (long)bz * NC_ * TN_;
    __syncthreads();
    float acc[8][4] = {};
    for (int kt = 0; kt < NC_; kt += 16) {
        #pragma unroll
        for (int i = 0; i < 8; i++) {
            int e = tid + i * 256;
            {   // A1 from z: mm fast (coalesced along m)
                int mm = e & 127, kk = e >> 7;
                int gk = kt + kk;
                float a1 = 0.f;
                if (gk < NC_) a1 = zb[(long)gk * TN_ + mz + mm] * G1[mm];
                u.p.A1[kk][mm] = a1;
            }
            {   // A2 from clc rows: kk fast
                int mm = e >> 4, kk = e & 15;
                int gk = kt + kk;
                float a2 = 0.f;
                if (gk < NC_) a2 = gcl[((long)m0 + mm) * NC_ + gk] * G2[mm];
                u.p.A2[kk][mm] = a2;
            }
            if (i < 4) {   // B tiles (16k x 64n each)
                int kk2 = e >> 6, nn = e & 63;
                int gk2 = kt + kk2, gn = n0 + nn;
                float b1 = 0.f, b2 = 0.f;
                if (gk2 < NC_ && gn < NC_) {
                    b1 = t1[gk2 * NC_ + gn];
                    b2 = t2[gk2 * NC_ + gn];
                }
                u.p.B1[kk2][nn] = b1;
                u.p.B2[kk2][nn] = b2;
            }
        }
        __syncthreads();
        #pragma unroll
        for (int kk = 0; kk < 16; kk++) {
            float4 a1l = *(const float4*)&u.p.A1[kk][ty * 4];
            float4 a1h = *(const float4*)&u.p.A1[kk][ty * 4 + 64];
            float4 a2l = *(const float4*)&u.p.A2[kk][ty * 4];
            float4 a2h = *(const float4*)&u.p.A2[kk][ty * 4 + 64];
            float4 b1v = *(const float4*)&u.p.B1[kk][tx * 4];
            float4 b2v = *(const float4*)&u.p.B2[kk][tx * 4];
            float a1[8] = {a1l.x, a1l.y, a1l.z, a1l.w,
                           a1h.x, a1h.y, a1h.z, a1h.w};
            float a2[8] = {a2l.x, a2l.y, a2l.z, a2l.w,
                           a2h.x, a2h.y, a2h.z, a2h.w};
            float b1[4] = {b1v.x, b1v.y, b1v.z, b1v.w};
            float b2[4] = {b2v.x, b2v.y, b2v.z, b2v.w};
            #pragma unroll
            for (int i = 0; i < 8; i++)
                #pragma unroll
                for (int j = 0; j < 4; j++)
                    acc[i][j] += a1[i] * b1[j] + a2[i] * b2[j];
        }
        __syncthreads();
    }
    // stage into Cs (load tiles dead after the loop's trailing barrier)
    #pragma unroll
    for (int i = 0; i < 8; i++) {
        int row = ty * 4 + (i >> 2) * 64 + (i & 3);
        #pragma unroll
        for (int j = 0; j < 4; j++)
            u.Cs[row][tx * 4 + j] = 0.5f * acc[i][j];
    }
    __syncthreads();
    for (int e = tid; e < 8192; e += 256) {
        int ml = e & 127, jl = e >> 7;      // ml lane-fast: coalesced scatter
        int j = n0 + jl;
        if (j >= NC_) continue;
        long r = m0 + ml;
        int b = (int)(r >> 14);
        int m = (int)(r & 16383);
        int tau = m >> 12;
        int n = m & 4095;
        float v = u.Cs[ml][jl];
        ocxz[((long)b * NC_ + j) * TN_ + m] = v;
        oasg[(((long)b * T_ + tau) * NC_ + j) * (long)N_ + n] = v;
    }
}

__global__ void softmax_k(const float* __restrict__ in, float* __restrict__ out) {
    long row = blockIdx.x;
    const float* r = in + row * N_;
    int tid = threadIdx.x;
    float v[16];
    float mx = -1e30f;
    #pragma unroll
    for (int i = 0; i < 16; i++) { v[i] = r[tid + i * 256]; mx = fmaxf(mx, v[i]); }
    mx = bmax(mx);
    float s = 0.f;
    #pragma unroll
    for (int i = 0; i < 16; i++) { v[i] = expf(v[i] - mx); s += v[i]; }
    s = bsum(s);
    float inv = 1.f / s;
    #pragma unroll
    for (int i = 0; i < 16; i++) out[row * N_ + tid + i * 256] = v[i] * inv;
}

// sum splitK partials + gate + C_in + LayerNorm. one block per (b, cluster).
__global__ void cin_k(const float* __restrict__ cenp,
                      const float* __restrict__ alpha, const float* __restrict__ beta,
                      const float* __restrict__ w, const float* __restrict__ bb,
                      float* __restrict__ cout) {
    int bx = blockIdx.x;
    int b = bx / NC_, kc = bx - b * NC_;
    int c = threadIdx.x;
    const long st = (long)NC_ * C_;           // T-slice stride
    const long pst = (long)(B_ * T_) * st;    // split-partial stride
    long base = (((long)b * T_) * NC_ + kc) * C_ + c;
    float p0 = 0.f, p1v = 0.f, p2v = 0.f, la = 0.f;
    #pragma unroll
    for (int p = 0; p < SPLITK_; p++) {
        const float* cp = cenp + (long)p * pst + base;
        p0  += cp[0];
        p1v += cp[st];
        p2v += cp[2 * st];
        la  += cp[3 * st];
    }
    float nl = bsum(la * la);
    float n0 = bsum(p0 * p0);
    float n1 = bsum(p1v * p1v);
    float n2 = bsum(p2v * p2v);
    float d0 = bsum(la * p0);
    float d1 = bsum(la * p1v);
    float d2 = bsum(la * p2v);
    float A = alpha[0], Bv = beta[0];
    float snl = sqrtf(nl);
    float g0 = 1.f / (1.f + expf(-(Bv + A * (d0 / fmaxf(snl * sqrtf(n0), 1e-8f)))));
    float g1 = 1.f / (1.f + expf(-(Bv + A * (d1 / fmaxf(snl * sqrtf(n1), 1e-8f)))));
    float g2 = 1.f / (1.f + expf(-(Bv + A * (d2 / fmaxf(snl * sqrtf(n2), 1e-8f)))));
    float ci = la + g0 * p0 + g1 * p1v + g2 * p2v;
    float mean = bsum(ci) * (1.f / 256.f);
    float dd = ci - mean;
    float var = bsum(dd * dd) * (1.f / 256.f);
    cout[((long)b * NC_ + kc) * C_ + c] = dd * rsqrtf(var + 1e-5f) * w[c] + bb[c];
}

// flash-style attention, 1 thread per query row, K/V in smem (nc=150, hd=32).
__global__ void __launch_bounds__(128) attn_k(
    const float* __restrict__ q, const float* __restrict__ kb,
    const float* __restrict__ vb, float* __restrict__ o) {
    int bh = blockIdx.y;
    int b = bh >> 3, h = bh & 7;
    __shared__ float Ks[NC_][HD_];
    __shared__ float Vs[NC_][HD_];
    int tid = threadIdx.x;
    for (int e = tid; e < NC_ * HD_; e += 128) {
        int kc = e >> 5, d = e & 31;
        long src = ((long)(b * NC_ + kc)) * C_ + h * HD_ + d;
        Ks[kc][d] = kb[src];
        Vs[kc][d] = vb[src];
    }
    __syncthreads();
    int n = blockIdx.x * 128 + tid;
    const float* qp = q + ((long)(b * N_ + n)) * C_ + h * HD_;
    float qr[32];
    #pragma unroll
    for (int d = 0; d < 32; d += 4) {
        float4 t = *(const float4*)(qp + d);
        qr[d] = t.x; qr[d + 1] = t.y; qr[d + 2] = t.z; qr[d + 3] = t.w;
    }
    float mval = -1e30f, l = 0.f, acc[32];
    #pragma unroll
    for (int d = 0; d < 32; d++) acc[d] = 0.f;
    for (int kc = 0; kc < NC_; kc++) {
        float s = 0.f;
        #pragma unroll
        for (int d = 0; d < 32; d++) s += qr[d] * Ks[kc][d];
        float nm = fmaxf(mval, s);
        float corr = expf(mval - nm);
        float p = expf(s - nm);
        l = l * corr + p;
        #pragma unroll
        for (int d = 0; d < 32; d++) acc[d] = acc[d] * corr + p * Vs[kc][d];
        mval = nm;
    }
    float inv = 1.f / l;
    float* op = o + ((long)(b * N_ + n)) * C_ + h * HD_;
    #pragma unroll
    for (int d = 0; d < 32; d += 4) {
        float4 t = {acc[d] * inv, acc[d + 1] * inv, acc[d + 2] * inv, acc[d + 3] * inv};
        *(float4*)(op + d) = t;
    }
}

// LayerNorm + residual. mode 0: out = res + LN(src); mode 1: out += LN(src).
__global__ void add_ln_k(const float* __restrict__ src, const float* __restrict__ res,
                         float* __restrict__ outp, const float* __restrict__ w,
                         const float* __restrict__ bb, int mode) {
    long row = blockIdx.x;
    int c = threadIdx.x;
    float v = src[row * C_ + c];
    float mean = bsum(v) * (1.f / 256.f);
    float dd = v - mean;
    float var = bsum(dd * dd) * (1.f / 256.f);
    float ln = dd * rsqrtf(var + 1e-5f) * w[c] + bb[c];
    if (mode == 0) outp[row * C_ + c] = res[row * C_ + c] + ln;
    else outp[row * C_ + c] += ln;
}

// depthwise 3x3 SAME conv, channel-last (pix, hid). 4-pixel x-strip per block.
__global__ void __launch_bounds__(256) conv4_k(
    const float* __restrict__ hin, const float* __restrict__ w,
    const float* __restrict__ bias, float* __restrict__ hout) {
    __shared__ float ws[HID_ * 9];
    int tid = threadIdx.x;
    for (int e = tid; e < HID_ * 9; e += 256) ws[e] = w[e];
    __syncthreads();
    int pix0 = blockIdx.x * 4;                 // 4 | 64, strip never wraps a row
    int b = pix0 >> 12, p = pix0 & 4095, y = p >> 6, x0 = p & 63;
    #pragma unroll
    for (int cc = 0; cc < 4; cc++) {
        int ch = tid + cc * 256;
        float wv[9];
        #pragma unroll
        for (int i = 0; i < 9; i++) wv[i] = ws[ch * 9 + i];
        float in[3][6];
        #pragma unroll
        for (int r = 0; r < 3; r++) {
            int yy = y - 1 + r;
            bool yok = (yy >= 0 && yy < IMG_);
            #pragma unroll
            for (int cxi = 0; cxi < 6; cxi++) {
                int xx = x0 - 1 + cxi;
                bool ok = yok && xx >= 0 && xx < IMG_;
                in[r][cxi] = ok
                    ? hin[((long)(b * N_ + yy * IMG_ + xx)) * HID_ + ch] : 0.f;
            }
        }
        float bv = bias[ch];
        #pragma unroll
        for (int px = 0; px < 4; px++) {
            float a = bv;
            #pragma unroll
            for (int r = 0; r < 3; r++)
                #pragma unroll
                for (int dx = 0; dx < 3; dx++)
                    a += wv[r * 3 + dx] * in[r][px + dx];
            hout[((long)(pix0 + px)) * HID_ + ch] = a;
        }
    }
}

// ---------------- host ----------------
static float* symaddr(const void* sym) {
    void* p = nullptr;
    cudaGetSymbolAddress(&p, sym);
    return (float*)p;
}

extern "C" void kernel_launch(void* const* d_in, const int* in_sizes, int n_in,
                              void* d_out, int out_size) {
    const float* x      = (const float*)d_in[0];
    const float* z      = (const float*)d_in[1];
    const float* mem    = (const float*)d_in[2];
    const float* cw     = (const float*)d_in[3];
    const float* p1     = (const float*)d_in[4];
    const float* tdt1   = (const float*)d_in[5];
    const float* p2     = (const float*)d_in[6];
    const float* tdt2   = (const float*)d_in[7];
    const float* alpha  = (const float*)d_in[8];
    const float* beta   = (const float*)d_in[9];
    const float* q_w    = (const float*)d_in[10];
    const float* q_b    = (const float*)d_in[11];
    const float* k_w    = (const float*)d_in[12];
    const float* k_b    = (const float*)d_in[13];
    const float* v_w    = (const float*)d_in[14];
    const float* v_b    = (const float*)d_in[15];
    const float* proj_w = (const float*)d_in[16];
    const float* proj_b = (const float*)d_in[17];
    const float* norm_w = (const float*)d_in[18];
    const float* norm_b = (const float*)d_in[19];
    const float* fc1_w  = (const float*)d_in[20];
    const float* fc1_b  = (const float*)d_in[21];
    const float* dw_w   = (const float*)d_in[22];
    const float* dw_b   = (const float*)d_in[23];
    const float* fc2_w  = (const float*)d_in[24];
    const float* fc2_b  = (const float*)d_in[25];

    float* xf   = symaddr(g_xf);
    float* clc  = symaddr(g_clc);
    float* gg1  = symaddr(g_g1);
    float* gg2  = symaddr(g_g2);
    float* soft = symaddr(g_soft);
    float* cenp = symaddr(g_cenp);
    float* cin  = symaddr(g_cin);
    float* kb   = symaddr(g_kb);
    float* vb   = symaddr(g_vb);
    float* qb   = symaddr(g_q);
    float* ao   = symaddr(g_ao);
    float* pj   = symaddr(g_pj);
    float* hb   = symaddr(g_h);
    float* h2   = symaddr(g_h2);
    float* p1h  = symaddr(g_p1h);
    float* p2h  = symaddr(g_p2h);

    float* out1 = (float*)d_out;                       // (B,N,C)
    float* out2 = out1 + (long)B_ * N_ * C_;           // cluster_x_z (B,nc,TN)
    float* out3 = out2 + (long)B_ * NC_ * TN_;         // assigned (B,T,nc,N)

    // 1) normalized prompts
    prompt_k<<<1, 256>>>(p1, p2, p1h, p2h);
    // 2) xf = concat(mem, x)
    build_xf_k<<<8192, 256>>>(x, mem, xf);
    // 3) cl = xf @ cw^T  -> clc rows (N-guarded 128x128 pipelined path)
    gemm128n_k<<<dim3(2, ROWS_ / 128), 256>>>(xf, cw, clc, NC_, C_);
    // 4) per-row gate factors (z read in place; no transpose materialization)
    gate_z_k<<<ROWS_ / 256, 256>>>(z, p1h, gg1);
    gate_c_k<<<4096, 256>>>(clc, p2h, gg2);
    // 5) dual tdt GEMM (128x64 tile, fused gates, direct z) -> outputs 2 & 3
    tdt_k<<<dim3(3, ROWS_ / 128), 256>>>(z, clc, gg1, gg2, tdt1, tdt2, out2, out3);
    // 6) softmax over N
    softmax_k<<<B_ * T_ * NC_, 256>>>(out3, soft);
    // 7) cen partials = soft @ xf (splitK=8, plain stores, no atomics)
    gemm_cen_k<<<dim3(2, 3, 64), 256>>>(soft, xf, cenp);
    // 8) sum partials + gate + C_in + LN
    cin_k<<<B_ * NC_, 256>>>(cenp, alpha, beta, norm_w, norm_b, cin);
    // 9/10) k, v projections
    gemm_k<true, false><<<dim3(4, 5, 1), 256>>>(cin, k_w, k_b, kb,
        B_ * NC_, C_, C_, 0, 0, 0, 1.f);
    gemm_k<true, false><<<dim3(4, 5, 1), 256>>>(cin, v_w, v_b, vb,
        B_ * NC_, C_, C_, 0, 0, 0, 1.f);
    // 11) q projection (scaled after bias) — 8192x256x256
    gemm128_k<false><<<dim3(2, 64), 256>>>(x, q_w, q_b, qb,
        C_, C_, 0.17677669529663689f);
    // 12) attention
    attn_k<<<dim3(N_ / 128, B_ * NH_), 128>>>(qb, kb, vb, ao);
    // 13) output projection — 8192x256x256
    gemm128_k<false><<<dim3(2, 64), 256>>>(ao, proj_w, proj_b, pj,
        C_, C_, 1.f);
    // 14) out = x + LN(proj)
    add_ln_k<<<B_ * N_, 256>>>(pj, x, out1, norm_w, norm_b, 0);
    // 15) fc1 — 8192x1024x256
    gemm128_k<false><<<dim3(8, 64), 256>>>(out1, fc1_w, fc1_b, hb,
        HID_, C_, 1.f);
    // 16) depthwise conv (4-pixel strips)
    conv4_k<<<B_ * N_ / 4, 256>>>(hb, dw_w, dw_b, h2);
    // 17) fc2 with exact GELU on A — 8192x256x1024
    gemm128_k<true><<<dim3(2, 64), 256>>>(h2, fc2_w, fc2_b, ao,
        C_, HID_, 1.f);
    // 18) out += LN(h)
    add_ln_k<<<B_ * N_, 256>>>(ao, nullptr, out1, norm_w, norm_b, 1);
}

// round 16
// speedup vs baseline: 1.0848x; 1.0848x over previous
#include <cuda_runtime.h>
#include <math.h>

// ---------------- constants ----------------
#define B_      2
#define N_      4096
#define C_      256
#define NC_     150
#define T_      4
#define TN_     16384          // T_*N_
#define ROWS_   32768          // B_*TN_
#define HID_    1024
#define NH_     8
#define HD_     32
#define IMG_    64
#define SPLITK_ 8

typedef unsigned long long u64p;   // packed f32x2

// packed fp32x2 helpers (Blackwell FFMA2 path; per-element .rn semantics)
__device__ __forceinline__ u64p f2pack(float lo, float hi) {
    u64p r;
    asm("mov.b64 %0, {%1, %2};" : "=l"(r) : "f"(lo), "f"(hi));
    return r;
}
__device__ __forceinline__ void f2fma(u64p& d, u64p a, u64p b) {
    asm("fma.rn.f32x2 %0, %1, %2, %0;" : "+l"(d) : "l"(a), "l"(b));
}
__device__ __forceinline__ float2 f2unpack(u64p v) {
    float lo, hi;
    asm("mov.b64 {%0, %1}, %2;" : "=f"(lo), "=f"(hi) : "l"(v));
    return make_float2(lo, hi);
}

// ---------------- scratch (device globals; no allocation) ----------------
__device__ float g_xf  [8u*4096u*256u];       // (B*T, N, C)
__device__ float g_clc [2u*16384u*150u];      // (B, TN, nc) rows (ungated)
__device__ float g_g1  [2u*16384u];           // per-row gate for z columns
__device__ float g_g2  [2u*16384u];           // per-row gate for clc
__device__ float g_soft[8u*150u*4096u];       // softmax(center)
__device__ float g_cenp[8u*8u*150u*256u];     // splitK partials: (split,B*T,nc,C)
__device__ float g_cin [2u*150u*256u];        // LN(C_in)
__device__ float g_kb  [2u*150u*256u];
__device__ float g_vb  [2u*150u*256u];
__device__ float g_q   [2u*4096u*256u];
__device__ float g_ao  [2u*4096u*256u];       // attention out, reused for fc2 out
__device__ float g_pj  [2u*4096u*256u];       // proj out
__device__ float g_h   [2u*4096u*1024u];      // fc1 out
__device__ float g_h2  [2u*4096u*1024u];      // conv out
__device__ float g_p1h [256];
__device__ float g_p2h [256];

// ---------------- reduction helpers (blockDim.x == 256) ----------------
__device__ __forceinline__ float bsum(float v) {
    __shared__ float sh[32];
    #pragma unroll
    for (int o = 16; o > 0; o >>= 1) v += __shfl_xor_sync(0xffffffffu, v, o);
    int lane = threadIdx.x & 31, w = threadIdx.x >> 5;
    if (lane == 0) sh[w] = v;
    __syncthreads();
    float r = (threadIdx.x < (blockDim.x >> 5)) ? sh[threadIdx.x] : 0.f;
    if (threadIdx.x < 32) {
        #pragma unroll
        for (int o = 16; o > 0; o >>= 1) r += __shfl_xor_sync(0xffffffffu, r, o);
    }
    if (threadIdx.x == 0) sh[0] = r;
    __syncthreads();
    r = sh[0];
    __syncthreads();
    return r;
}

__device__ __forceinline__ float bmax(float v) {
    __shared__ float sh[32];
    #pragma unroll
    for (int o = 16; o > 0; o >>= 1) v = fmaxf(v, __shfl_xor_sync(0xffffffffu, v, o));
    int lane = threadIdx.x & 31, w = threadIdx.x >> 5;
    if (lane == 0) sh[w] = v;
    __syncthreads();
    float r = (threadIdx.x < (blockDim.x >> 5)) ? sh[threadIdx.x] : -1e30f;
    if (threadIdx.x < 32) {
        #pragma unroll
        for (int o = 16; o > 0; o >>= 1) r = fmaxf(r, __shfl_xor_sync(0xffffffffu, r, o));
    }
    if (threadIdx.x == 0) sh[0] = r;
    __syncthreads();
    r = sh[0];
    __syncthreads();
    return r;
}

// ---------------- generic tiled GEMM (64x64x16, 256 thr, 4x4 microtile) ----
// used only for the small k/v projections.
template<bool TRB, bool GELUA>
__global__ void __launch_bounds__(256) gemm_k(
    const float* __restrict__ A, const float* __restrict__ Bp,
    const float* __restrict__ bias, float* __restrict__ Cp,
    int M, int Nn, int K, long sA, long sB, long sC,
    float postscale)
{
    int batch = blockIdx.z;
    const float* Ab = A + (long)batch * sA;
    const float* Bb = Bp + (long)batch * sB;
    float* Cb = Cp + (long)batch * sC;
    int m0 = blockIdx.y * 64, n0 = blockIdx.x * 64;
    __shared__ float As[16][64];
    __shared__ float Bs[16][64];
    int tid = threadIdx.x;
    int tx = tid & 15, ty = tid >> 4;
    float acc[4][4] = {};
    for (int kb = 0; kb < K; kb += 16) {
        #pragma unroll
        for (int i = 0; i < 4; i++) {
            int e = tid + i * 256;
            int mm = e >> 4, kk = e & 15;
            int gm = m0 + mm;
            float v = 0.f;
            if (gm < M) v = Ab[(long)gm * K + kb + kk];
            if (GELUA) v = 0.5f * v * (1.f + erff(v * 0.70710678118654752f));
            As[kk][mm] = v;
        }
        #pragma unroll
        for (int i = 0; i < 4; i++) {
            int e = tid + i * 256;
            if (TRB) {
                int nn = e >> 4, kk = e & 15;
                int gn = n0 + nn;
                Bs[kk][nn] = (gn < Nn) ? Bb[(long)gn * K + kb + kk] : 0.f;
            } else {
                int kk = e >> 6, nn = e & 63;
                int gn = n0 + nn;
                Bs[kk][nn] = (gn < Nn) ? Bb[(long)(kb + kk) * Nn + gn] : 0.f;
            }
        }
        __syncthreads();
        #pragma unroll
        for (int kk = 0; kk < 16; kk++) {
            float4 av = *(const float4*)&As[kk][ty * 4];
            float4 bv = *(const float4*)&Bs[kk][tx * 4];
            float a[4] = {av.x, av.y, av.z, av.w};
            float b[4] = {bv.x, bv.y, bv.z, bv.w};
            #pragma unroll
            for (int i = 0; i < 4; i++)
                #pragma unroll
                for (int j = 0; j < 4; j++)
                    acc[i][j] += a[i] * b[j];
        }
        __syncthreads();
    }
    #pragma unroll
    for (int i = 0; i < 4; i++) {
        int gm = m0 + ty * 4 + i;
        if (gm >= M) continue;
        #pragma unroll
        for (int j = 0; j < 4; j++) {
            int gn = n0 + tx * 4 + j;
            if (gn >= Nn) continue;
            float v = acc[i][j];
            if (bias) v += bias[gn];
            Cb[(long)gm * Nn + gn] = v * postscale;
        }
    }
}

// ---------------- cen GEMM (64m x 128n x 16k, f32x2 accumulators) ----------
__global__ void __launch_bounds__(256) gemm_cen_k(
    const float* __restrict__ A, const float* __restrict__ Bx,
    float* __restrict__ Cp)
{
    int zb = blockIdx.z;
    int batch = zb / SPLITK_;
    int ks = zb - batch * SPLITK_;
    const int kLen = N_ / SPLITK_;           // 512
    const float* Ab = A + (long)batch * NC_ * N_;
    const float* Bb = Bx + (long)batch * N_ * C_;
    float* Cb = Cp + ((long)ks * (B_ * T_) + batch) * NC_ * C_;
    int m0 = blockIdx.y * 64, n0 = blockIdx.x * 128;
    __shared__ float As[16][68];
    __shared__ float Bs[16][132];
    const int tid = threadIdx.x;
    const int tx = tid & 15, ty = tid >> 4;
    const int amm = tid >> 2, ak4 = (tid & 3) * 4;
    const bool aok = (m0 + amm) < NC_;
    const int bk0 = tid >> 5,        bn0 = (tid & 31) * 4;
    const int bk1 = (tid + 256) >> 5, bn1 = ((tid + 256) & 31) * 4;
    u64p acc2[4][4] = {};
    int kbeg = ks * kLen;
    const float4 z4 = {0.f, 0.f, 0.f, 0.f};
    float4 pa = aok ? *(const float4*)&Ab[(long)(m0 + amm) * N_ + kbeg + ak4] : z4;
    float4 pb0 = *(const float4*)&Bb[(long)(kbeg + bk0) * C_ + n0 + bn0];
    float4 pb1 = *(const float4*)&Bb[(long)(kbeg + bk1) * C_ + n0 + bn1];
    for (int kt = 0; kt < kLen; kt += 16) {
        As[ak4 + 0][amm] = pa.x;
        As[ak4 + 1][amm] = pa.y;
        As[ak4 + 2][amm] = pa.z;
        As[ak4 + 3][amm] = pa.w;
        *(float4*)&Bs[bk0][bn0] = pb0;
        *(float4*)&Bs[bk1][bn1] = pb1;
        __syncthreads();
        if (kt + 16 < kLen) {
            int kb = kbeg + kt + 16;
            pa = aok ? *(const float4*)&Ab[(long)(m0 + amm) * N_ + kb + ak4] : z4;
            pb0 = *(const float4*)&Bb[(long)(kb + bk0) * C_ + n0 + bn0];
            pb1 = *(const float4*)&Bb[(long)(kb + bk1) * C_ + n0 + bn1];
        }
        #pragma unroll
        for (int kk = 0; kk < 16; kk++) {
            float4 a0 = *(const float4*)&As[kk][ty * 4];
            float4 b0 = *(const float4*)&Bs[kk][tx * 4];
            float4 b1 = *(const float4*)&Bs[kk][tx * 4 + 64];
            u64p bb[4] = {f2pack(b0.x, b0.y), f2pack(b0.z, b0.w),
                          f2pack(b1.x, b1.y), f2pack(b1.z, b1.w)};
            float a[4] = {a0.x, a0.y, a0.z, a0.w};
            #pragma unroll
            for (int i = 0; i < 4; i++) {
                u64p ai = f2pack(a[i], a[i]);
                #pragma unroll
                for (int j = 0; j < 4; j++) f2fma(acc2[i][j], ai, bb[j]);
            }
        }
        __syncthreads();
    }
    #pragma unroll
    for (int i = 0; i < 4; i++) {
        int gm = m0 + ty * 4 + i;
        if (gm >= NC_) continue;
        float* crow = Cb + (long)gm * C_ + n0;
        #pragma unroll
        for (int jh = 0; jh < 2; jh++) {
            int cb = tx * 4 + jh * 64;
            float2 p0 = f2unpack(acc2[i][jh * 2 + 0]);
            float2 p1 = f2unpack(acc2[i][jh * 2 + 1]);
            float4 v = {p0.x, p0.y, p1.x, p1.y};
            *(float4*)&crow[cb] = v;
        }
    }
}

// ---------------- big tiled GEMM (128x128x16, f32x2 accumulators) ----------
template<bool GELUA>
__global__ void __launch_bounds__(256, 2) gemm128_k(
    const float* __restrict__ A, const float* __restrict__ Bp,
    const float* __restrict__ bias, float* __restrict__ Cp,
    int Nn, int K, float postscale)
{
    const int m0 = blockIdx.y * 128, n0 = blockIdx.x * 128;
    __shared__ float As[16][132];
    __shared__ float Bs[16][132];
    const int tid = threadIdx.x;
    const int tx = tid & 15, ty = tid >> 4;
    const int mm0 = tid >> 2, k40 = (tid & 3) * 4;
    const int mm1 = (tid + 256) >> 2, k41 = ((tid + 256) & 3) * 4;
    u64p acc2[8][4] = {};
    float4 pa0, pa1, pb0, pb1;
    pa0 = *(const float4*)&A [(long)(m0 + mm0) * K + k40];
    pa1 = *(const float4*)&A [(long)(m0 + mm1) * K + k41];
    pb0 = *(const float4*)&Bp[(long)(n0 + mm0) * K + k40];
    pb1 = *(const float4*)&Bp[(long)(n0 + mm1) * K + k41];
    for (int kb = 0; kb < K; kb += 16) {
        float4 va0 = pa0, va1 = pa1;
        if (GELUA) {
            va0.x = 0.5f * va0.x * (1.f + erff(va0.x * 0.70710678118654752f));
            va0.y = 0.5f * va0.y * (1.f + erff(va0.y * 0.70710678118654752f));
            va0.z = 0.5f * va0.z * (1.f + erff(va0.z * 0.70710678118654752f));
            va0.w = 0.5f * va0.w * (1.f + erff(va0.w * 0.70710678118654752f));
            va1.x = 0.5f * va1.x * (1.f + erff(va1.x * 0.70710678118654752f));
            va1.y = 0.5f * va1.y * (1.f + erff(va1.y * 0.70710678118654752f));
            va1.z = 0.5f * va1.z * (1.f + erff(va1.z * 0.70710678118654752f));
            va1.w = 0.5f * va1.w * (1.f + erff(va1.w * 0.70710678118654752f));
        }
        As[k40 + 0][mm0] = va0.x; As[k40 + 1][mm0] = va0.y;
        As[k40 + 2][mm0] = va0.z; As[k40 + 3][mm0] = va0.w;
        As[k41 + 0][mm1] = va1.x; As[k41 + 1][mm1] = va1.y;
        As[k41 + 2][mm1] = va1.z; As[k41 + 3][mm1] = va1.w;
        Bs[k40 + 0][mm0] = pb0.x; Bs[k40 + 1][mm0] = pb0.y;
        Bs[k40 + 2][mm0] = pb0.z; Bs[k40 + 3][mm0] = pb0.w;
        Bs[k41 + 0][mm1] = pb1.x; Bs[k41 + 1][mm1] = pb1.y;
        Bs[k41 + 2][mm1] = pb1.z; Bs[k41 + 3][mm1] = pb1.w;
        __syncthreads();
        if (kb + 16 < K) {
            int kn = kb + 16;
            pa0 = *(const float4*)&A [(long)(m0 + mm0) * K + kn + k40];
            pa1 = *(const float4*)&A [(long)(m0 + mm1) * K + kn + k41];
            pb0 = *(const float4*)&Bp[(long)(n0 + mm0) * K + kn + k40];
            pb1 = *(const float4*)&Bp[(long)(n0 + mm1) * K + kn + k41];
        }
        #pragma unroll
        for (int kk = 0; kk < 16; kk++) {
            float4 a0 = *(const float4*)&As[kk][ty * 4];
            float4 a1 = *(const float4*)&As[kk][ty * 4 + 64];
            float4 b0 = *(const float4*)&Bs[kk][tx * 4];
            float4 b1 = *(const float4*)&Bs[kk][tx * 4 + 64];
            u64p bb[4] = {f2pack(b0.x, b0.y), f2pack(b0.z, b0.w),
                          f2pack(b1.x, b1.y), f2pack(b1.z, b1.w)};
            float a[8] = {a0.x, a0.y, a0.z, a0.w, a1.x, a1.y, a1.z, a1.w};
            #pragma unroll
            for (int i = 0; i < 8; i++) {
                u64p ai = f2pack(a[i], a[i]);
                #pragma unroll
                for (int j = 0; j < 4; j++) f2fma(acc2[i][j], ai, bb[j]);
            }
        }
        __syncthreads();
    }
    #pragma unroll
    for (int ih = 0; ih < 2; ih++) {
        #pragma unroll
        for (int ii = 0; ii < 4; ii++) {
            int r = ih * 4 + ii;
            int gm = m0 + ty * 4 + ih * 64 + ii;
            float* crow = Cp + (long)gm * Nn + n0;
            #pragma unroll
            for (int jh = 0; jh < 2; jh++) {
                int cb = tx * 4 + jh * 64;
                float2 p0 = f2unpack(acc2[r][jh * 2 + 0]);
                float2 p1 = f2unpack(acc2[r][jh * 2 + 1]);
                float4 v = {p0.x, p0.y, p1.x, p1.y};
                if (bias) {
                    v.x += bias[n0 + cb + 0];
                    v.y += bias[n0 + cb + 1];
                    v.z += bias[n0 + cb + 2];
                    v.w += bias[n0 + cb + 3];
                }
                v.x *= postscale; v.y *= postscale;
                v.z *= postscale; v.w *= postscale;
                *(float4*)&crow[cb] = v;
            }
        }
    }
}

// ---------------- N-guarded 128x128 GEMM (f32x2 accumulators) ---------------
__global__ void __launch_bounds__(256, 2) gemm128n_k(
    const float* __restrict__ A, const float* __restrict__ Bp,
    float* __restrict__ Cp, int Nn, int K)
{
    const int m0 = blockIdx.y * 128, n0 = blockIdx.x * 128;
    __shared__ float As[16][132];
    __shared__ float Bs[16][132];
    const int tid = threadIdx.x;
    const int tx = tid & 15, ty = tid >> 4;
    const int mm0 = tid >> 2, k40 = (tid & 3) * 4;
    const int mm1 = (tid + 256) >> 2, k41 = ((tid + 256) & 3) * 4;
    const bool b0ok = (n0 + mm0 < Nn);
    const bool b1ok = (n0 + mm1 < Nn);
    u64p acc2[8][4] = {};
    float4 pa0, pa1, pb0, pb1;
    const float4 z4 = {0.f, 0.f, 0.f, 0.f};
    pa0 = *(const float4*)&A[(long)(m0 + mm0) * K + k40];
    pa1 = *(const float4*)&A[(long)(m0 + mm1) * K + k41];
    pb0 = b0ok ? *(const float4*)&Bp[(long)(n0 + mm0) * K + k40] : z4;
    pb1 = b1ok ? *(const float4*)&Bp[(long)(n0 + mm1) * K + k41] : z4;
    for (int kb = 0; kb < K; kb += 16) {
        As[k40 + 0][mm0] = pa0.x; As[k40 + 1][mm0] = pa0.y;
        As[k40 + 2][mm0] = pa0.z; As[k40 + 3][mm0] = pa0.w;
        As[k41 + 0][mm1] = pa1.x; As[k41 + 1][mm1] = pa1.y;
        As[k41 + 2][mm1] = pa1.z; As[k41 + 3][mm1] = pa1.w;
        Bs[k40 + 0][mm0] = pb0.x; Bs[k40 + 1][mm0] = pb0.y;
        Bs[k40 + 2][mm0] = pb0.z; Bs[k40 + 3][mm0] = pb0.w;
        Bs[k41 + 0][mm1] = pb1.x; Bs[k41 + 1][mm1] = pb1.y;
        Bs[k41 + 2][mm1] = pb1.z; Bs[k41 + 3][mm1] = pb1.w;
        __syncthreads();
        if (kb + 16 < K) {
            int kn = kb + 16;
            pa0 = *(const float4*)&A[(long)(m0 + mm0) * K + kn + k40];
            pa1 = *(const float4*)&A[(long)(m0 + mm1) * K + kn + k41];
            pb0 = b0ok ? *(const float4*)&Bp[(long)(n0 + mm0) * K + kn + k40] : z4;
            pb1 = b1ok ? *(const float4*)&Bp[(long)(n0 + mm1) * K + kn + k41] : z4;
        }
        #pragma unroll
        for (int kk = 0; kk < 16; kk++) {
            float4 a0 = *(const float4*)&As[kk][ty * 4];
            float4 a1 = *(const float4*)&As[kk][ty * 4 + 64];
            float4 b0 = *(const float4*)&Bs[kk][tx * 4];
            float4 b1 = *(const float4*)&Bs[kk][tx * 4 + 64];
            u64p bb[4] = {f2pack(b0.x, b0.y), f2pack(b0.z, b0.w),
                          f2pack(b1.x, b1.y), f2pack(b1.z, b1.w)};
            float a[8] = {a0.x, a0.y, a0.z, a0.w, a1.x, a1.y, a1.z, a1.w};
            #pragma unroll
            for (int i = 0; i < 8; i++) {
                u64p ai = f2pack(a[i], a[i]);
                #pragma unroll
                for (int j = 0; j < 4; j++) f2fma(acc2[i][j], ai, bb[j]);
            }
        }
        __syncthreads();
    }
    #pragma unroll
    for (int ih = 0; ih < 2; ih++) {
        #pragma unroll
        for (int ii = 0; ii < 4; ii++) {
            int r = ih * 4 + ii;
            int gm = m0 + ty * 4 + ih * 64 + ii;
            float* crow = Cp + (long)gm * Nn;
            #pragma unroll
            for (int jh = 0; jh < 2; jh++) {
                float2 p0 = f2unpack(acc2[r][jh * 2 + 0]);
                float2 p1 = f2unpack(acc2[r][jh * 2 + 1]);
                float c[4] = {p0.x, p0.y, p1.x, p1.y};
                #pragma unroll
                for (int jj = 0; jj < 4; jj++) {
                    int gn = n0 + tx * 4 + jh * 64 + jj;
                    if (gn < Nn) crow[gn] = c[jj];
                }
            }
        }
    }
}

// ---------------- misc kernels ----------------
__global__ void prompt_k(const float* __restrict__ p1, const float* __restrict__ p2,
                         float* p1h, float* p2h) {
    int c = threadIdx.x;
    float v1 = (c < NC_) ? p1[c] : 0.f;
    float v2 = (c < NC_) ? p2[c] : 0.f;
    float s1 = bsum(v1 * v1);
    float s2 = bsum(v2 * v2);
    if (c < NC_) {
        p1h[c] = v1 / fmaxf(sqrtf(s1), 1e-12f);
        p2h[c] = v2 / fmaxf(sqrtf(s2), 1e-12f);
    }
}

__global__ void build_xf_k(const float* __restrict__ x, const float* __restrict__ mem,
                           float* __restrict__ xf) {
    long idx = (long)blockIdx.x * 256 + threadIdx.x;
    long e = idx * 4;
    long r = e >> 8;
    int c = (int)(e & 255);
    int b = (int)(r >> 14);
    int rem = (int)(r & 16383);
    int tau = rem >> 12;
    int n = rem & 4095;
    const float* src = (tau < 3)
        ? mem + ((((long)(b * 3 + tau)) * N_ + n) << 8) + c
        : x + ((((long)b) * N_ + n) << 8) + c;
    *(float4*)(xf + e) = *(const float4*)src;
}

// gate over z columns. 4 threads per row (k-split), 64 rows/block, smem reduce.
__global__ void gate_z_k(const float* __restrict__ z,
                         const float* __restrict__ p1h, float* __restrict__ gg1) {
    __shared__ float ph[NC_];
    __shared__ float sss[4][64];
    __shared__ float sdp[4][64];
    int tid = threadIdx.x;
    if (tid < NC_) ph[tid] = p1h[tid];
    __syncthreads();
    int rl = tid & 63;          // row within block
    int kp = tid >> 6;          // k partition 0..3
    long r = (long)blockIdx.x * 64 + rl;
    int b = (int)(r >> 14);
    int m = (int)(r & 16383);
    const float* zp = z + (long)b * NC_ * TN_ + m;
    float ss = 0.f, dp = 0.f;
    for (int k = kp; k < NC_; k += 4) {
        float v = zp[(long)k * TN_];
        ss += v * v; dp += v * ph[k];
    }
    sss[kp][rl] = ss;
    sdp[kp][rl] = dp;
    __syncthreads();
    if (tid < 64) {
        float S = sss[0][tid] + sss[1][tid] + sss[2][tid] + sss[3][tid];
        float D = sdp[0][tid] + sdp[1][tid] + sdp[2][tid] + sdp[3][tid];
        float g = D / fmaxf(sqrtf(S), 1e-12f);
        gg1[(long)blockIdx.x * 64 + tid] = fminf(fmaxf(g, 0.f), 1.f);
    }
}

// gate over clc rows (row-major). 8 warps/block, 1 row/warp.
__global__ void gate_c_k(const float* __restrict__ clc,
                         const float* __restrict__ p2h, float* __restrict__ gg2) {
    int w = threadIdx.x >> 5, lane = threadIdx.x & 31;
    long r = (long)blockIdx.x * 8 + w;
    const float* row = clc + r * NC_;
    float ss = 0.f, dp = 0.f;
    #pragma unroll
    for (int i = 0; i < 5; i++) {
        int k = lane + i * 32;
        float v = (k < NC_) ? row[k] : 0.f;
        float pk = (k < NC_) ? p2h[k] : 0.f;
        ss += v * v; dp += v * pk;
    }
    #pragma unroll
    for (int o = 16; o > 0; o >>= 1) {
        ss += __shfl_xor_sync(0xffffffffu, ss, o);
        dp += __shfl_xor_sync(0xffffffffu, dp, o);
    }
    float g = dp / fmaxf(sqrtf(ss), 1e-12f);
    g = fminf(fmaxf(g, 0.f), 1.f);
    if (lane == 0) gg2[r] = g;
}

// dual GEMM: 0.5*((g1.zT)@tdt1 + (g2.clc)@tdt2). 128m x 64n tile,
// f32x2 accumulators, smem union for scatter staging.
__global__ void __launch_bounds__(256) tdt_k(
    const float* __restrict__ z, const float* __restrict__ gcl,
    const float* __restrict__ gg1, const float* __restrict__ gg2,
    const float* __restrict__ t1, const float* __restrict__ t2,
    float* __restrict__ ocxz, float* __restrict__ oasg)
{
    __shared__ union {
        struct {
            float A1[16][132];
            float A2[16][132];
            float B1[16][64];
            float B2[16][64];
        } p;
        float Cs[128][65];
    } u;
    __shared__ float G1[128], G2[128];
    int m0 = blockIdx.y * 128, n0 = blockIdx.x * 64;
    int tid = threadIdx.x, tx = tid & 15, ty = tid >> 4;
    if (tid < 128) {
        G1[tid] = gg1[m0 + tid];
        G2[tid] = gg2[m0 + tid];
    }
    const int bz = m0 >> 14;
    const int mz = m0 & 16383;
    const float* zb = z + (long)bz * NC_ * TN_;
    __syncthreads();
    u64p acc2[8][2] = {};
    for (int kt = 0; kt < NC_; kt += 16) {
        #pragma unroll
        for (int i = 0; i < 8; i++) {
            int e = tid + i * 256;
            {   // A1 from z: mm fast (coalesced along m)
                int mm = e & 127, kk = e >> 7;
                int gk = kt + kk;
                float a1 = 0.f;
                if (gk < NC_) a1 = zb[(long)gk * TN_ + mz + mm] * G1[mm];
                u.p.A1[kk][mm] = a1;
            }
            {   // A2 from clc rows: kk fast
                int mm = e >> 4, kk = e & 15;
                int gk = kt + kk;
                float a2 = 0.f;
                if (gk < NC_) a2 = gcl[((long)m0 + mm) * NC_ + gk] * G2[mm];
                u.p.A2[kk][mm] = a2;
            }
            if (i < 4) {   // B tiles
                int kk2 = e >> 6, nn = e & 63;
                int gk2 = kt + kk2, gn = n0 + nn;
                float b1 = 0.f, b2 = 0.f;
                if (gk2 < NC_ && gn < NC_) {
                    b1 = t1[gk2 * NC_ + gn];
                    b2 = t2[gk2 * NC_ + gn];
                }
                u.p.B1[kk2][nn] = b1;
                u.p.B2[kk2][nn] = b2;
            }
        }
        __syncthreads();
        #pragma unroll
        for (int kk = 0; kk < 16; kk++) {
            float4 a1l = *(const float4*)&u.p.A1[kk][ty * 4];
            float4 a1h = *(const float4*)&u.p.A1[kk][ty * 4 + 64];
            float4 a2l = *(const float4*)&u.p.A2[kk][ty * 4];
            float4 a2h = *(const float4*)&u.p.A2[kk][ty * 4 + 64];
            float4 b1v = *(const float4*)&u.p.B1[kk][tx * 4];
            float4 b2v = *(const float4*)&u.p.B2[kk][tx * 4];
            u64p bb1[2] = {f2pack(b1v.x, b1v.y), f2pack(b1v.z, b1v.w)};
            u64p bb2[2] = {f2pack(b2v.x, b2v.y), f2pack(b2v.z, b2v.w)};
            float a1[8] = {a1l.x, a1l.y, a1l.z, a1l.w,
                           a1h.x, a1h.y, a1h.z, a1h.w};
            float a2[8] = {a2l.x, a2l.y, a2l.z, a2l.w,
                           a2h.x, a2h.y, a2h.z, a2h.w};
            #pragma unroll
            for (int i = 0; i < 8; i++) {
                u64p ai1 = f2pack(a1[i], a1[i]);
                u64p ai2 = f2pack(a2[i], a2[i]);
                f2fma(acc2[i][0], ai1, bb1[0]);
                f2fma(acc2[i][1], ai1, bb1[1]);
                f2fma(acc2[i][0], ai2, bb2[0]);
                f2fma(acc2[i][1], ai2, bb2[1]);
            }
        }
        __syncthreads();
    }
    // stage into Cs (load tiles dead after the loop's trailing barrier)
    #pragma unroll
    for (int i = 0; i < 8; i++) {
        int row = ty * 4 + (i >> 2) * 64 + (i & 3);
        float2 p0 = f2unpack(acc2[i][0]);
        float2 p1 = f2unpack(acc2[i][1]);
        u.Cs[row][tx * 4 + 0] = 0.5f * p0.x;
        u.Cs[row][tx * 4 + 1] = 0.5f * p0.y;
        u.Cs[row][tx * 4 + 2] = 0.5f * p1.x;
        u.Cs[row][tx * 4 + 3] = 0.5f * p1.y;
    }
    __syncthreads();
    for (int e = tid; e < 8192; e += 256) {
        int ml = e & 127, jl = e >> 7;
        int j = n0 + jl;
        if (j >= NC_) continue;
        long r = m0 + ml;
        int b = (int)(r >> 14);
        int m = (int)(r & 16383);
        int tau = m >> 12;
        int n = m & 4095;
        float v = u.Cs[ml][jl];
        ocxz[((long)b * NC_ + j) * TN_ + m] = v;
        oasg[(((long)b * T_ + tau) * NC_ + j) * (long)N_ + n] = v;
    }
}

__global__ void softmax_k(const float* __restrict__ in, float* __restrict__ out) {
    long row = blockIdx.x;
    const float* r = in + row * N_;
    int tid = threadIdx.x;
    float v[16];
    float mx = -1e30f;
    #pragma unroll
    for (int i = 0; i < 16; i++) { v[i] = r[tid + i * 256]; mx = fmaxf(mx, v[i]); }
    mx = bmax(mx);
    float s = 0.f;
    #pragma unroll
    for (int i = 0; i < 16; i++) { v[i] = expf(v[i] - mx); s += v[i]; }
    s = bsum(s);
    float inv = 1.f / s;
    #pragma unroll
    for (int i = 0; i < 16; i++) out[row * N_ + tid + i * 256] = v[i] * inv;
}

// sum splitK partials + gate + C_in + LayerNorm. one block per (b, cluster).
__global__ void cin_k(const float* __restrict__ cenp,
                      const float* __restrict__ alpha, const float* __restrict__ beta,
                      const float* __restrict__ w, const float* __restrict__ bb,
                      float* __restrict__ cout) {
    int bx = blockIdx.x;
    int b = bx / NC_, kc = bx - b * NC_;
    int c = threadIdx.x;
    const long st = (long)NC_ * C_;
    const long pst = (long)(B_ * T_) * st;
    long base = (((long)b * T_) * NC_ + kc) * C_ + c;
    float p0 = 0.f, p1v = 0.f, p2v = 0.f, la = 0.f;
    #pragma unroll
    for (int p = 0; p < SPLITK_; p++) {
        const float* cp = cenp + (long)p * pst + base;
        p0  += cp[0];
        p1v += cp[st];
        p2v += cp[2 * st];
        la  += cp[3 * st];
    }
    float nl = bsum(la * la);
    float n0 = bsum(p0 * p0);
    float n1 = bsum(p1v * p1v);
    float n2 = bsum(p2v * p2v);
    float d0 = bsum(la * p0);
    float d1 = bsum(la * p1v);
    float d2 = bsum(la * p2v);
    float A = alpha[0], Bv = beta[0];
    float snl = sqrtf(nl);
    float g0 = 1.f / (1.f + expf(-(Bv + A * (d0 / fmaxf(snl * sqrtf(n0), 1e-8f)))));
    float g1 = 1.f / (1.f + expf(-(Bv + A * (d1 / fmaxf(snl * sqrtf(n1), 1e-8f)))));
    float g2 = 1.f / (1.f + expf(-(Bv + A * (d2 / fmaxf(snl * sqrtf(n2), 1e-8f)))));
    float ci = la + g0 * p0 + g1 * p1v + g2 * p2v;
    float mean = bsum(ci) * (1.f / 256.f);
    float dd = ci - mean;
    float var = bsum(dd * dd) * (1.f / 256.f);
    cout[((long)b * NC_ + kc) * C_ + c] = dd * rsqrtf(var + 1e-5f) * w[c] + bb[c];
}

// flash-style attention, 1 thread per query row, K/V in smem (nc=150, hd=32).
__global__ void __launch_bounds__(128) attn_k(
    const float* __restrict__ q, const float* __restrict__ kb,
    const float* __restrict__ vb, float* __restrict__ o) {
    int bh = blockIdx.y;
    int b = bh >> 3, h = bh & 7;
    __shared__ float Ks[NC_][HD_];
    __shared__ float Vs[NC_][HD_];
    int tid = threadIdx.x;
    for (int e = tid; e < NC_ * HD_; e += 128) {
        int kc = e >> 5, d = e & 31;
        long src = ((long)(b * NC_ + kc)) * C_ + h * HD_ + d;
        Ks[kc][d] = kb[src];
        Vs[kc][d] = vb[src];
    }
    __syncthreads();
    int n = blockIdx.x * 128 + tid;
    const float* qp = q + ((long)(b * N_ + n)) * C_ + h * HD_;
    float qr[32];
    #pragma unroll
    for (int d = 0; d < 32; d += 4) {
        float4 t = *(const float4*)(qp + d);
        qr[d] = t.x; qr[d + 1] = t.y; qr[d + 2] = t.z; qr[d + 3] = t.w;
    }
    float mval = -1e30f, l = 0.f, acc[32];
    #pragma unroll
    for (int d = 0; d < 32; d++) acc[d] = 0.f;
    for (int kc = 0; kc < NC_; kc++) {
        float s = 0.f;
        #pragma unroll
        for (int d = 0; d < 32; d++) s += qr[d] * Ks[kc][d];
        float nm = fmaxf(mval, s);
        float corr = expf(mval - nm);
        float p = expf(s - nm);
        l = l * corr + p;
        #pragma unroll
        for (int d = 0; d < 32; d++) acc[d] = acc[d] * corr + p * Vs[kc][d];
        mval = nm;
    }
    float inv = 1.f / l;
    float* op = o + ((long)(b * N_ + n)) * C_ + h * HD_;
    #pragma unroll
    for (int d = 0; d < 32; d += 4) {
        float4 t = {acc[d] * inv, acc[d + 1] * inv, acc[d + 2] * inv, acc[d + 3] * inv};
        *(float4*)(op + d) = t;
    }
}

// LayerNorm + residual. mode 0: out = res + LN(src); mode 1: out += LN(src).
__global__ void add_ln_k(const float* __restrict__ src, const float* __restrict__ res,
                         float* __restrict__ outp, const float* __restrict__ w,
                         const float* __restrict__ bb, int mode) {
    long row = blockIdx.x;
    int c = threadIdx.x;
    float v = src[row * C_ + c];
    float mean = bsum(v) * (1.f / 256.f);
    float dd = v - mean;
    float var = bsum(dd * dd) * (1.f / 256.f);
    float ln = dd * rsqrtf(var + 1e-5f) * w[c] + bb[c];
    if (mode == 0) outp[row * C_ + c] = res[row * C_ + c] + ln;
    else outp[row * C_ + c] += ln;
}

// depthwise 3x3 SAME conv, channel-last (pix, hid). 4-pixel x-strip per block.
__global__ void __launch_bounds__(256) conv4_k(
    const float* __restrict__ hin, const float* __restrict__ w,
    const float* __restrict__ bias, float* __restrict__ hout) {
    __shared__ float ws[HID_ * 9];
    int tid = threadIdx.x;
    for (int e = tid; e < HID_ * 9; e += 256) ws[e] = w[e];
    __syncthreads();
    int pix0 = blockIdx.x * 4;                 // 4 | 64, strip never wraps a row
    int b = pix0 >> 12, p = pix0 & 4095, y = p >> 6, x0 = p & 63;
    #pragma unroll
    for (int cc = 0; cc < 4; cc++) {
        int ch = tid + cc * 256;
        float wv[9];
        #pragma unroll
        for (int i = 0; i < 9; i++) wv[i] = ws[ch * 9 + i];
        float in[3][6];
        #pragma unroll
        for (int r = 0; r < 3; r++) {
            int yy = y - 1 + r;
            bool yok = (yy >= 0 && yy < IMG_);
            #pragma unroll
            for (int cxi = 0; cxi < 6; cxi++) {
                int xx = x0 - 1 + cxi;
                bool ok = yok && xx >= 0 && xx < IMG_;
                in[r][cxi] = ok
                    ? hin[((long)(b * N_ + yy * IMG_ + xx)) * HID_ + ch] : 0.f;
            }
        }
        float bv = bias[ch];
        #pragma unroll
        for (int px = 0; px < 4; px++) {
            float a = bv;
            #pragma unroll
            for (int r = 0; r < 3; r++)
                #pragma unroll
                for (int dx = 0; dx < 3; dx++)
                    a += wv[r * 3 + dx] * in[r][px + dx];
            hout[((long)(pix0 + px)) * HID_ + ch] = a;
        }
    }
}

// ---------------- host ----------------
static float* symaddr(const void* sym) {
    void* p = nullptr;
    cudaGetSymbolAddress(&p, sym);
    return (float*)p;
}

extern "C" void kernel_launch(void* const* d_in, const int* in_sizes, int n_in,
                              void* d_out, int out_size) {
    const float* x      = (const float*)d_in[0];
    const float* z      = (const float*)d_in[1];
    const float* mem    = (const float*)d_in[2];
    const float* cw     = (const float*)d_in[3];
    const float* p1     = (const float*)d_in[4];
    const float* tdt1   = (const float*)d_in[5];
    const float* p2     = (const float*)d_in[6];
    const float* tdt2   = (const float*)d_in[7];
    const float* alpha  = (const float*)d_in[8];
    const float* beta   = (const float*)d_in[9];
    const float* q_w    = (const float*)d_in[10];
    const float* q_b    = (const float*)d_in[11];
    const float* k_w    = (const float*)d_in[12];
    const float* k_b    = (const float*)d_in[13];
    const float* v_w    = (const float*)d_in[14];
    const float* v_b    = (const float*)d_in[15];
    const float* proj_w = (const float*)d_in[16];
    const float* proj_b = (const float*)d_in[17];
    const float* norm_w = (const float*)d_in[18];
    const float* norm_b = (const float*)d_in[19];
    const float* fc1_w  = (const float*)d_in[20];
    const float* fc1_b  = (const float*)d_in[21];
    const float* dw_w   = (const float*)d_in[22];
    const float* dw_b   = (const float*)d_in[23];
    const float* fc2_w  = (const float*)d_in[24];
    const float* fc2_b  = (const float*)d_in[25];

    float* xf   = symaddr(g_xf);
    float* clc  = symaddr(g_clc);
    float* gg1  = symaddr(g_g1);
    float* gg2  = symaddr(g_g2);
    float* soft = symaddr(g_soft);
    float* cenp = symaddr(g_cenp);
    float* cin  = symaddr(g_cin);
    float* kb   = symaddr(g_kb);
    float* vb   = symaddr(g_vb);
    float* qb   = symaddr(g_q);
    float* ao   = symaddr(g_ao);
    float* pj   = symaddr(g_pj);
    float* hb   = symaddr(g_h);
    float* h2   = symaddr(g_h2);
    float* p1h  = symaddr(g_p1h);
    float* p2h  = symaddr(g_p2h);

    float* out1 = (float*)d_out;                       // (B,N,C)
    float* out2 = out1 + (long)B_ * N_ * C_;           // cluster_x_z (B,nc,TN)
    float* out3 = out2 + (long)B_ * NC_ * TN_;         // assigned (B,T,nc,N)

    // 1) normalized prompts
    prompt_k<<<1, 256>>>(p1, p2, p1h, p2h);
    // 2) xf = concat(mem, x)
    build_xf_k<<<8192, 256>>>(x, mem, xf);
    // 3) cl = xf @ cw^T  -> clc rows
    gemm128n_k<<<dim3(2, ROWS_ / 128), 256>>>(xf, cw, clc, NC_, C_);
    // 4) per-row gate factors
    gate_z_k<<<ROWS_ / 64, 256>>>(z, p1h, gg1);
    gate_c_k<<<4096, 256>>>(clc, p2h, gg2);
    // 5) dual tdt GEMM -> outputs 2 & 3
    tdt_k<<<dim3(3, ROWS_ / 128), 256>>>(z, clc, gg1, gg2, tdt1, tdt2, out2, out3);
    // 6) softmax over N
    softmax_k<<<B_ * T_ * NC_, 256>>>(out3, soft);
    // 7) cen partials = soft @ xf (splitK=8, plain stores)
    gemm_cen_k<<<dim3(2, 3, 64), 256>>>(soft, xf, cenp);
    // 8) sum partials + gate + C_in + LN
    cin_k<<<B_ * NC_, 256>>>(cenp, alpha, beta, norm_w, norm_b, cin);
    // 9/10) k, v projections
    gemm_k<true, false><<<dim3(4, 5, 1), 256>>>(cin, k_w, k_b, kb,
        B_ * NC_, C_, C_, 0, 0, 0, 1.f);
    gemm_k<true, false><<<dim3(4, 5, 1), 256>>>(cin, v_w, v_b, vb,
        B_ * NC_, C_, C_, 0, 0, 0, 1.f);
    // 11) q projection — 8192x256x256
    gemm128_k<false><<<dim3(2, 64), 256>>>(x, q_w, q_b, qb,
        C_, C_, 0.17677669529663689f);
    // 12) attention
    attn_k<<<dim3(N_ / 128, B_ * NH_), 128>>>(qb, kb, vb, ao);
    // 13) output projection — 8192x256x256
    gemm128_k<false><<<dim3(2, 64), 256>>>(ao, proj_w, proj_b, pj,
        C_, C_, 1.f);
    // 14) out = x + LN(proj)
    add_ln_k<<<B_ * N_, 256>>>(pj, x, out1, norm_w, norm_b, 0);
    // 15) fc1 — 8192x1024x256
    gemm128_k<false><<<dim3(8, 64), 256>>>(out1, fc1_w, fc1_b, hb,
        HID_, C_, 1.f);
    // 16) depthwise conv (4-pixel strips)
    conv4_k<<<B_ * N_ / 4, 256>>>(hb, dw_w, dw_b, h2);
    // 17) fc2 with exact GELU on A — 8192x256x1024
    gemm128_k<true><<<dim3(2, 64), 256>>>(h2, fc2_w, fc2_b, ao,
        C_, HID_, 1.f);
    // 18) out += LN(h)
    add_ln_k<<<B_ * N_, 256>>>(ao, nullptr, out1, norm_w, norm_b, 1);
}